// round 1
// baseline (speedup 1.0000x reference)
#include <cuda_runtime.h>

// Problem sizes (fixed by the dataset)
#define B_  16
#define T_  1024
#define C_  1024
#define M_  (B_ * T_)   // 16384 rows

// Scratch (no cudaMalloc allowed) — 3 x 64 MB
__device__ float g_k[M_ * C_];
__device__ float g_r[M_ * C_];
__device__ float g_s[M_ * C_];

// -----------------------------------------------------------------------------
// SGEMM (NT): out[m][n] = sum_k A[m][k] * W[n][k]
// A: [M,1024] row-major, W: [1024,1024] row-major. M, N multiples of 128.
// 128x128 tile, BK=8, 256 threads, 8x8 per thread.
// -----------------------------------------------------------------------------
__global__ __launch_bounds__(256, 2)
void sgemm_nt(const float* __restrict__ A, const float* __restrict__ W,
              float* __restrict__ Out)
{
    __shared__ float As[8][128];
    __shared__ float Bs[8][128];

    const int bm = blockIdx.y * 128;
    const int bn = blockIdx.x * 128;
    const int tid = threadIdx.x;
    const int tx = tid & 15;        // 0..15 -> n
    const int ty = tid >> 4;        // 0..15 -> m

    // loader mapping: each thread loads one float4 of A and one of W per chunk
    const int lr = tid >> 1;            // 0..127 (tile row)
    const int lc = (tid & 1) * 4;       // 0 or 4 (k offset)

    const float* Ap = A + (size_t)(bm + lr) * C_ + lc;
    const float* Wp = W + (size_t)(bn + lr) * C_ + lc;

    float acc[8][8];
#pragma unroll
    for (int i = 0; i < 8; i++)
#pragma unroll
        for (int j = 0; j < 8; j++) acc[i][j] = 0.f;

    for (int k0 = 0; k0 < C_; k0 += 8) {
        float4 av = *(const float4*)(Ap + k0);
        float4 wv = *(const float4*)(Wp + k0);
        __syncthreads();
        As[lc + 0][lr] = av.x; As[lc + 1][lr] = av.y;
        As[lc + 2][lr] = av.z; As[lc + 3][lr] = av.w;
        Bs[lc + 0][lr] = wv.x; Bs[lc + 1][lr] = wv.y;
        Bs[lc + 2][lr] = wv.z; Bs[lc + 3][lr] = wv.w;
        __syncthreads();

#pragma unroll
        for (int kk = 0; kk < 8; kk++) {
            float a[8], b[8];
            float4 a0 = *(const float4*)&As[kk][ty * 8];
            float4 a1 = *(const float4*)&As[kk][ty * 8 + 4];
            float4 b0 = *(const float4*)&Bs[kk][tx * 8];
            float4 b1 = *(const float4*)&Bs[kk][tx * 8 + 4];
            a[0]=a0.x; a[1]=a0.y; a[2]=a0.z; a[3]=a0.w;
            a[4]=a1.x; a[5]=a1.y; a[6]=a1.z; a[7]=a1.w;
            b[0]=b0.x; b[1]=b0.y; b[2]=b0.z; b[3]=b0.w;
            b[4]=b1.x; b[5]=b1.y; b[6]=b1.z; b[7]=b1.w;
#pragma unroll
            for (int i = 0; i < 8; i++)
#pragma unroll
                for (int j = 0; j < 8; j++)
                    acc[i][j] = fmaf(a[i], b[j], acc[i][j]);
        }
    }

#pragma unroll
    for (int i = 0; i < 8; i++) {
        float* op = Out + (size_t)(bm + ty * 8 + i) * C_ + bn + tx * 8;
#pragma unroll
        for (int j = 0; j < 8; j += 4) {
            float4 v = make_float4(acc[i][j], acc[i][j+1], acc[i][j+2], acc[i][j+3]);
            *(float4*)(op + j) = v;
        }
    }
}

// -----------------------------------------------------------------------------
// WKV scan: one thread per (b, c) channel; sequential over T.
// Reads g_k, g_r; writes g_s = sigmoid(r) * y.
// -----------------------------------------------------------------------------
__global__ __launch_bounds__(256)
void wkv_scan_kernel(const float* __restrict__ time_decay,
                     const float* __restrict__ time_first)
{
    const int gid = blockIdx.x * blockDim.x + threadIdx.x;   // 0..16383
    const int b = gid >> 10;
    const int c = gid & (C_ - 1);

    const float w = -__expf(time_decay[c]);
    const float u = time_first[c];

    float a = 0.f, bden = 0.f, pp = -1e38f;

    const float* kp = g_k + (size_t)b * T_ * C_ + c;
    const float* rp = g_r + (size_t)b * T_ * C_ + c;
    float*       sp = g_s + (size_t)b * T_ * C_ + c;

#pragma unroll 4
    for (int t = 0; t < T_; t++) {
        const float kt = kp[(size_t)t * C_];
        const float rt = rp[(size_t)t * C_];
        const float vt = rt;                      // v = receptance(x) per source

        // output
        float ww = u + kt;
        float q  = fmaxf(pp, ww);
        float e1 = __expf(pp - q);
        float e2 = __expf(ww - q);
        float y  = (e1 * a + e2 * vt) / (e1 * bden + e2);

        // state update
        float ww2 = pp + w;
        float q2  = fmaxf(ww2, kt);
        float e1b = __expf(ww2 - q2);
        float e2b = __expf(kt - q2);
        a    = e1b * a + e2b * vt;
        bden = e1b * bden + e2b;
        pp   = q2;

        // fused gate
        float sig = 1.f / (1.f + __expf(-rt));
        sp[(size_t)t * C_] = sig * y;
    }
}

// -----------------------------------------------------------------------------
// Launch
// -----------------------------------------------------------------------------
extern "C" void kernel_launch(void* const* d_in, const int* in_sizes, int n_in,
                              void* d_out, int out_size)
{
    const float* x  = (const float*)d_in[0];
    const float* Wk = (const float*)d_in[1];
    const float* Wr = (const float*)d_in[2];
    const float* Wo = (const float*)d_in[3];
    const float* td = (const float*)d_in[4];
    const float* tf = (const float*)d_in[5];
    float* out = (float*)d_out;

    float* gk; cudaGetSymbolAddress((void**)&gk, g_k);
    float* gr; cudaGetSymbolAddress((void**)&gr, g_r);
    float* gs; cudaGetSymbolAddress((void**)&gs, g_s);

    dim3 grid(C_ / 128, M_ / 128);
    sgemm_nt<<<grid, 256>>>(x, Wk, gk);
    sgemm_nt<<<grid, 256>>>(x, Wr, gr);
    wkv_scan_kernel<<<(B_ * C_) / 256, 256>>>(td, tf);
    sgemm_nt<<<grid, 256>>>(gs, Wo, out);
}

// round 3
// speedup vs baseline: 3.5529x; 3.5529x over previous
#include <cuda_runtime.h>
#include <cuda_bf16.h>
#include <cstdint>

#define B_  16
#define T_  1024
#define C_  1024
#define M_  (B_ * T_)   // 16384

// ---------------- scratch (__device__ globals; no cudaMalloc) ----------------
__device__ __nv_bfloat16 g_xh[M_ * C_];
__device__ __nv_bfloat16 g_xl[M_ * C_];
__device__ __nv_bfloat16 g_wkh[C_ * C_], g_wkl[C_ * C_];
__device__ __nv_bfloat16 g_wrh[C_ * C_], g_wrl[C_ * C_];
__device__ __nv_bfloat16 g_woh[C_ * C_], g_wol[C_ * C_];
__device__ float g_k[M_ * C_];
__device__ float g_r[M_ * C_];
__device__ __nv_bfloat16 g_sh[M_ * C_];
__device__ __nv_bfloat16 g_sl[M_ * C_];

// ---------------- helpers ----------------
__device__ __forceinline__ uint32_t smem_u32(const void* p) {
    uint32_t a;
    asm("{ .reg .u64 t; cvta.to.shared.u64 t, %1; cvt.u32.u64 %0, t; }" : "=r"(a) : "l"(p));
    return a;
}
__device__ __forceinline__ void cp_async16(uint32_t s, const void* g) {
    asm volatile("cp.async.cg.shared.global [%0], [%1], 16;" :: "r"(s), "l"(g) : "memory");
}
__device__ __forceinline__ void cp_commit() {
    asm volatile("cp.async.commit_group;" ::: "memory");
}
template<int N> __device__ __forceinline__ void cp_wait() {
    asm volatile("cp.async.wait_group %0;" :: "n"(N) : "memory");
}
__device__ __forceinline__ void ldmatrix4(uint32_t& r0, uint32_t& r1, uint32_t& r2, uint32_t& r3, uint32_t addr) {
    asm volatile("ldmatrix.sync.aligned.m8n8.x4.shared.b16 {%0,%1,%2,%3}, [%4];"
                 : "=r"(r0), "=r"(r1), "=r"(r2), "=r"(r3) : "r"(addr));
}
__device__ __forceinline__ void mma16816(float& c0, float& c1, float& c2, float& c3,
                                         uint32_t a0, uint32_t a1, uint32_t a2, uint32_t a3,
                                         uint32_t b0, uint32_t b1) {
    asm volatile("mma.sync.aligned.m16n8k16.row.col.f32.bf16.bf16.f32 "
                 "{%0,%1,%2,%3}, {%4,%5,%6,%7}, {%8,%9}, {%0,%1,%2,%3};"
                 : "+f"(c0), "+f"(c1), "+f"(c2), "+f"(c3)
                 : "r"(a0), "r"(a1), "r"(a2), "r"(a3), "r"(b0), "r"(b1));
}
__device__ __forceinline__ uint32_t sw128(uint32_t o) { return o ^ ((o >> 3) & 0x70); }

// ---------------- bf16x3 HMMA GEMM (NT): Out[m][n] = sum_k A[m][k]*W[n][k] ----------------
#define BM 128
#define BN 128
#define BK 64
#define STAGES 3
#define NCHPASS (C_ / BK)        // 16
#define NCHUNK  (3 * NCHPASS)    // 48
#define STAGE_BYTES (BM * 128 + BN * 128)   // 32768 (A then B, 128B rows)
#define SMEM_GEMM (STAGES * STAGE_BYTES)    // 98304

__global__ __launch_bounds__(256, 2)
void gemm_bf16x3(const __nv_bfloat16* __restrict__ Ah, const __nv_bfloat16* __restrict__ Al,
                 const __nv_bfloat16* __restrict__ Wh, const __nv_bfloat16* __restrict__ Wl,
                 float* __restrict__ Out)
{
    extern __shared__ char smem[];
    const uint32_t sb = smem_u32(smem);
    const int tid = threadIdx.x;
    const int wid = tid >> 5;
    const int lane = tid & 31;
    const int bm = blockIdx.y * BM;
    const int bn = blockIdx.x * BN;

    const int wm = (wid >> 2) * 64;   // warp m offset (0 or 64)
    const int wn = (wid & 3) * 32;    // warp n offset

    float acc[4][4][4];
#pragma unroll
    for (int i = 0; i < 4; i++)
#pragma unroll
        for (int j = 0; j < 4; j++)
#pragma unroll
            for (int c = 0; c < 4; c++) acc[i][j][c] = 0.f;

    // loader: 256 threads, A stage = 1024 x 16B chunks, B same
    auto load_chunk = [&](int ch, int stage) {
        const int pass = ch / NCHPASS;
        const int k0 = (ch % NCHPASS) * BK;
        const __nv_bfloat16* As = (pass == 1) ? Al : Ah;
        const __nv_bfloat16* Ws = (pass == 2) ? Wl : Wh;
        const uint32_t abase = sb + stage * STAGE_BYTES;
        const uint32_t bbase = abase + BM * 128;
#pragma unroll
        for (int i = 0; i < 4; i++) {
            int q = tid + i * 256;
            int row = q >> 3, c = q & 7;
            cp_async16(abase + sw128(row * 128 + c * 16),
                       As + (size_t)(bm + row) * C_ + k0 + c * 8);
        }
#pragma unroll
        for (int i = 0; i < 4; i++) {
            int q = tid + i * 256;
            int row = q >> 3, c = q & 7;
            cp_async16(bbase + sw128(row * 128 + c * 16),
                       Ws + (size_t)(bn + row) * C_ + k0 + c * 8);
        }
    };

    load_chunk(0, 0); cp_commit();
    load_chunk(1, 1); cp_commit();

    // lane-invariant pieces of ldmatrix addressing
    const int lrowA = (lane & 7) + ((lane >> 3) & 1) * 8;   // row within 16-row tile
    const int lkbA  = ((lane >> 3) >> 1) * 16;              // 0 or 16 bytes
    const int lrowB = (lane & 7) + ((lane >> 3) >> 1) * 8;
    const int lkbB  = ((lane >> 3) & 1) * 16;

    for (int ch = 0; ch < NCHUNK; ch++) {
        cp_wait<STAGES - 2>();
        __syncthreads();
        if (ch + STAGES - 1 < NCHUNK) load_chunk(ch + STAGES - 1, (ch + STAGES - 1) % STAGES);
        cp_commit();

        const uint32_t abase = sb + (ch % STAGES) * STAGE_BYTES;
        const uint32_t bbase = abase + BM * 128;

#pragma unroll
        for (int ks = 0; ks < 4; ks++) {
            uint32_t a[4][4], b[2][4];
#pragma unroll
            for (int mt = 0; mt < 4; mt++) {
                int r = wm + mt * 16 + lrowA;
                ldmatrix4(a[mt][0], a[mt][1], a[mt][2], a[mt][3],
                          abase + sw128(r * 128 + ks * 32 + lkbA));
            }
#pragma unroll
            for (int nt2 = 0; nt2 < 2; nt2++) {
                int r = wn + nt2 * 16 + lrowB;
                ldmatrix4(b[nt2][0], b[nt2][1], b[nt2][2], b[nt2][3],
                          bbase + sw128(r * 128 + ks * 32 + lkbB));
            }
#pragma unroll
            for (int mt = 0; mt < 4; mt++) {
#pragma unroll
                for (int nt = 0; nt < 4; nt++) {
                    uint32_t b0 = b[nt >> 1][(nt & 1) * 2 + 0];
                    uint32_t b1 = b[nt >> 1][(nt & 1) * 2 + 1];
                    mma16816(acc[mt][nt][0], acc[mt][nt][1], acc[mt][nt][2], acc[mt][nt][3],
                             a[mt][0], a[mt][1], a[mt][2], a[mt][3], b0, b1);
                }
            }
        }
    }

    // epilogue: direct fp32 stores
#pragma unroll
    for (int mt = 0; mt < 4; mt++) {
        int row0 = bm + wm + mt * 16 + (lane >> 2);
#pragma unroll
        for (int nt = 0; nt < 4; nt++) {
            int col = bn + wn + nt * 8 + (lane & 3) * 2;
            float2* p0 = (float2*)(Out + (size_t)row0 * C_ + col);
            float2* p1 = (float2*)(Out + (size_t)(row0 + 8) * C_ + col);
            *p0 = make_float2(acc[mt][nt][0], acc[mt][nt][1]);
            *p1 = make_float2(acc[mt][nt][2], acc[mt][nt][3]);
        }
    }
}

// ---------------- fp32 -> bf16 hi/lo split ----------------
__global__ __launch_bounds__(256)
void split_bf16(const float* __restrict__ in, __nv_bfloat16* __restrict__ hi,
                __nv_bfloat16* __restrict__ lo, int n4)
{
    int i = blockIdx.x * blockDim.x + threadIdx.x;
    if (i >= n4) return;
    float4 v = ((const float4*)in)[i];
    __nv_bfloat16 h0 = __float2bfloat16(v.x), h1 = __float2bfloat16(v.y);
    __nv_bfloat16 h2 = __float2bfloat16(v.z), h3 = __float2bfloat16(v.w);
    __nv_bfloat162 hp0{h0, h1}, hp1{h2, h3};
    __nv_bfloat162 lp0{__float2bfloat16(v.x - __bfloat162float(h0)),
                       __float2bfloat16(v.y - __bfloat162float(h1))};
    __nv_bfloat162 lp1{__float2bfloat16(v.z - __bfloat162float(h2)),
                       __float2bfloat16(v.w - __bfloat162float(h3))};
    ((__nv_bfloat162*)hi)[i * 2 + 0] = hp0;
    ((__nv_bfloat162*)hi)[i * 2 + 1] = hp1;
    ((__nv_bfloat162*)lo)[i * 2 + 0] = lp0;
    ((__nv_bfloat162*)lo)[i * 2 + 1] = lp1;
}

// ---------------- WKV scan: prefetch-pipelined, fused gate + bf16 split ----------------
#define PF 8
__global__ __launch_bounds__(128)
void wkv_scan_kernel(const float* __restrict__ time_decay,
                     const float* __restrict__ time_first)
{
    const int gid = blockIdx.x * blockDim.x + threadIdx.x;   // 0..16383
    const int b = gid >> 10;
    const int c = gid & (C_ - 1);

    const float w = -__expf(time_decay[c]);
    const float u = time_first[c];

    float a = 0.f, bden = 0.f, pp = -1e38f;

    const float* kp = g_k + (size_t)b * T_ * C_ + c;
    const float* rp = g_r + (size_t)b * T_ * C_ + c;
    __nv_bfloat16* shp = g_sh + (size_t)b * T_ * C_ + c;
    __nv_bfloat16* slp = g_sl + (size_t)b * T_ * C_ + c;

    float kbuf[PF], rbuf[PF];
#pragma unroll
    for (int i = 0; i < PF; i++) {
        kbuf[i] = kp[(size_t)i * C_];
        rbuf[i] = rp[(size_t)i * C_];
    }

#pragma unroll 8
    for (int t = 0; t < T_; t++) {
        const float kt = kbuf[t & (PF - 1)];
        const float rt = rbuf[t & (PF - 1)];
        if (t + PF < T_) {
            kbuf[t & (PF - 1)] = kp[(size_t)(t + PF) * C_];
            rbuf[t & (PF - 1)] = rp[(size_t)(t + PF) * C_];
        }
        const float vt = rt;

        float ww = u + kt;
        float q  = fmaxf(pp, ww);
        float e1 = __expf(pp - q);
        float e2 = __expf(ww - q);
        float y  = (e1 * a + e2 * vt) / (e1 * bden + e2);

        float ww2 = pp + w;
        float q2  = fmaxf(ww2, kt);
        float e1b = __expf(ww2 - q2);
        float e2b = __expf(kt - q2);
        a    = e1b * a + e2b * vt;
        bden = e1b * bden + e2b;
        pp   = q2;

        float sig = 1.f / (1.f + __expf(-rt));
        float s = sig * y;
        __nv_bfloat16 h = __float2bfloat16(s);
        shp[(size_t)t * C_] = h;
        slp[(size_t)t * C_] = __float2bfloat16(s - __bfloat162float(h));
    }
}

// ---------------- launch ----------------
extern "C" void kernel_launch(void* const* d_in, const int* in_sizes, int n_in,
                              void* d_out, int out_size)
{
    const float* x  = (const float*)d_in[0];
    const float* Wk = (const float*)d_in[1];
    const float* Wr = (const float*)d_in[2];
    const float* Wo = (const float*)d_in[3];
    const float* td = (const float*)d_in[4];
    const float* tf = (const float*)d_in[5];
    float* out = (float*)d_out;

    __nv_bfloat16 *xh, *xl, *wkh, *wkl, *wrh, *wrl, *woh, *wol, *sh, *sl;
    float *gk, *gr;
    cudaGetSymbolAddress((void**)&xh, g_xh);   cudaGetSymbolAddress((void**)&xl, g_xl);
    cudaGetSymbolAddress((void**)&wkh, g_wkh); cudaGetSymbolAddress((void**)&wkl, g_wkl);
    cudaGetSymbolAddress((void**)&wrh, g_wrh); cudaGetSymbolAddress((void**)&wrl, g_wrl);
    cudaGetSymbolAddress((void**)&woh, g_woh); cudaGetSymbolAddress((void**)&wol, g_wol);
    cudaGetSymbolAddress((void**)&sh, g_sh);   cudaGetSymbolAddress((void**)&sl, g_sl);
    cudaGetSymbolAddress((void**)&gk, g_k);    cudaGetSymbolAddress((void**)&gr, g_r);

    cudaFuncSetAttribute(gemm_bf16x3, cudaFuncAttributeMaxDynamicSharedMemorySize, SMEM_GEMM);

    split_bf16<<<(M_ * C_ / 4 + 255) / 256, 256>>>(x, xh, xl, M_ * C_ / 4);
    split_bf16<<<(C_ * C_ / 4 + 255) / 256, 256>>>(Wk, wkh, wkl, C_ * C_ / 4);
    split_bf16<<<(C_ * C_ / 4 + 255) / 256, 256>>>(Wr, wrh, wrl, C_ * C_ / 4);
    split_bf16<<<(C_ * C_ / 4 + 255) / 256, 256>>>(Wo, woh, wol, C_ * C_ / 4);

    dim3 grid(C_ / BN, M_ / BM);   // (8, 128)
    gemm_bf16x3<<<grid, 256, SMEM_GEMM>>>(xh, xl, wkh, wkl, gk);
    gemm_bf16x3<<<grid, 256, SMEM_GEMM>>>(xh, xl, wrh, wrl, gr);
    wkv_scan_kernel<<<(B_ * C_) / 128, 128>>>(td, tf);
    gemm_bf16x3<<<grid, 256, SMEM_GEMM>>>(sh, sl, woh, wol, out);
}

// round 5
// speedup vs baseline: 5.2062x; 1.4653x over previous
#include <cuda_runtime.h>
#include <cuda_fp16.h>
#include <cstdint>

#define B_  16
#define T_  1024
#define C_  1024
#define M_  (B_ * T_)   // 16384

// ---------------- scratch ----------------
__device__ __half g_xh[M_ * C_];
__device__ __half g_xl[M_ * C_];
__device__ __half g_wk[C_ * C_];
__device__ __half g_wr[C_ * C_];
__device__ __half g_wo[C_ * C_];
__device__ float g_k[M_ * C_];
__device__ float g_r[M_ * C_];
__device__ __half g_sh[M_ * C_];
__device__ __half g_sl[M_ * C_];

// ---------------- helpers ----------------
__device__ __forceinline__ uint32_t smem_u32(const void* p) {
    uint32_t a;
    asm("{ .reg .u64 t; cvta.to.shared.u64 t, %1; cvt.u32.u64 %0, t; }" : "=r"(a) : "l"(p));
    return a;
}
__device__ __forceinline__ void cp_async16(uint32_t s, const void* g) {
    asm volatile("cp.async.cg.shared.global [%0], [%1], 16;" :: "r"(s), "l"(g) : "memory");
}
__device__ __forceinline__ void cp_commit() {
    asm volatile("cp.async.commit_group;" ::: "memory");
}
template<int N> __device__ __forceinline__ void cp_wait() {
    asm volatile("cp.async.wait_group %0;" :: "n"(N) : "memory");
}
__device__ __forceinline__ void ldmatrix4(uint32_t& r0, uint32_t& r1, uint32_t& r2, uint32_t& r3, uint32_t addr) {
    asm volatile("ldmatrix.sync.aligned.m8n8.x4.shared.b16 {%0,%1,%2,%3}, [%4];"
                 : "=r"(r0), "=r"(r1), "=r"(r2), "=r"(r3) : "r"(addr));
}
__device__ __forceinline__ void mma16816(float& c0, float& c1, float& c2, float& c3,
                                         uint32_t a0, uint32_t a1, uint32_t a2, uint32_t a3,
                                         uint32_t b0, uint32_t b1) {
    asm volatile("mma.sync.aligned.m16n8k16.row.col.f32.f16.f16.f32 "
                 "{%0,%1,%2,%3}, {%4,%5,%6,%7}, {%8,%9}, {%0,%1,%2,%3};"
                 : "+f"(c0), "+f"(c1), "+f"(c2), "+f"(c3)
                 : "r"(a0), "r"(a1), "r"(a2), "r"(a3), "r"(b0), "r"(b1));
}
__device__ __forceinline__ uint32_t sw128(uint32_t o) { return o ^ ((o >> 3) & 0x70); }

// ---------------- fp16 2-term GEMM (NT), W-shared fused passes ----------------
// Out[m][n] = sum_k (Ah[m][k] + Al[m][k]) * W[n][k], fp32 accum.
#define BM 128
#define BN 128
#define BK 64
#define NCHUNK (C_ / BK)                    // 16
#define TILE_B (128 * 128)                  // 16KB per tile (128 rows x 128B)
#define STAGE_BYTES (3 * TILE_B)            // Ah, Al, W  = 48KB
#define SMEM_GEMM (2 * STAGE_BYTES)         // 96KB, 2 stages

__global__ __launch_bounds__(256, 2)
void gemm_fp16x2(const __half* __restrict__ Ah, const __half* __restrict__ Al,
                 const __half* __restrict__ W, float* __restrict__ Out)
{
    extern __shared__ char smem[];
    const uint32_t sb = smem_u32(smem);
    const int tid = threadIdx.x;
    const int wid = tid >> 5;
    const int lane = tid & 31;
    const int bm = blockIdx.y * BM;
    const int bn = blockIdx.x * BN;

    const int wm = (wid >> 2) * 64;   // warp m offset
    const int wn = (wid & 3) * 32;    // warp n offset

    float acc[4][4][4];
#pragma unroll
    for (int i = 0; i < 4; i++)
#pragma unroll
        for (int j = 0; j < 4; j++)
#pragma unroll
            for (int c = 0; c < 4; c++) acc[i][j][c] = 0.f;

    auto load_chunk = [&](int ch, int stage) {
        const int k0 = ch * BK;
        const uint32_t base = sb + stage * STAGE_BYTES;
#pragma unroll
        for (int i = 0; i < 4; i++) {
            int q = tid + i * 256;
            int row = q >> 3, c = q & 7;
            uint32_t so = sw128(row * 128 + c * 16);
            cp_async16(base + so, Ah + (size_t)(bm + row) * C_ + k0 + c * 8);
            cp_async16(base + TILE_B + so, Al + (size_t)(bm + row) * C_ + k0 + c * 8);
            cp_async16(base + 2 * TILE_B + so, W + (size_t)(bn + row) * C_ + k0 + c * 8);
        }
    };

    load_chunk(0, 0);
    cp_commit();

    const int lrowA = (lane & 7) + ((lane >> 3) & 1) * 8;
    const int lkbA  = ((lane >> 3) >> 1) * 16;
    const int lrowB = (lane & 7) + ((lane >> 3) >> 1) * 8;
    const int lkbB  = ((lane >> 3) & 1) * 16;

    for (int ch = 0; ch < NCHUNK; ch++) {
        if (ch + 1 < NCHUNK) load_chunk(ch + 1, (ch + 1) & 1);
        cp_commit();
        cp_wait<1>();
        __syncthreads();

        const uint32_t base = sb + (ch & 1) * STAGE_BYTES;

#pragma unroll
        for (int ks = 0; ks < 4; ks++) {
            uint32_t b[2][4];
#pragma unroll
            for (int nt2 = 0; nt2 < 2; nt2++) {
                int r = wn + nt2 * 16 + lrowB;
                ldmatrix4(b[nt2][0], b[nt2][1], b[nt2][2], b[nt2][3],
                          base + 2 * TILE_B + sw128(r * 128 + ks * 32 + lkbB));
            }
            {   // hi pass
                uint32_t a[4][4];
#pragma unroll
                for (int mt = 0; mt < 4; mt++) {
                    int r = wm + mt * 16 + lrowA;
                    ldmatrix4(a[mt][0], a[mt][1], a[mt][2], a[mt][3],
                              base + sw128(r * 128 + ks * 32 + lkbA));
                }
#pragma unroll
                for (int mt = 0; mt < 4; mt++)
#pragma unroll
                    for (int nt = 0; nt < 4; nt++)
                        mma16816(acc[mt][nt][0], acc[mt][nt][1], acc[mt][nt][2], acc[mt][nt][3],
                                 a[mt][0], a[mt][1], a[mt][2], a[mt][3],
                                 b[nt >> 1][(nt & 1) * 2 + 0], b[nt >> 1][(nt & 1) * 2 + 1]);
            }
            {   // lo pass (same W frags, same accumulators)
                uint32_t a[4][4];
#pragma unroll
                for (int mt = 0; mt < 4; mt++) {
                    int r = wm + mt * 16 + lrowA;
                    ldmatrix4(a[mt][0], a[mt][1], a[mt][2], a[mt][3],
                              base + TILE_B + sw128(r * 128 + ks * 32 + lkbA));
                }
#pragma unroll
                for (int mt = 0; mt < 4; mt++)
#pragma unroll
                    for (int nt = 0; nt < 4; nt++)
                        mma16816(acc[mt][nt][0], acc[mt][nt][1], acc[mt][nt][2], acc[mt][nt][3],
                                 a[mt][0], a[mt][1], a[mt][2], a[mt][3],
                                 b[nt >> 1][(nt & 1) * 2 + 0], b[nt >> 1][(nt & 1) * 2 + 1]);
            }
        }
        __syncthreads();
    }

#pragma unroll
    for (int mt = 0; mt < 4; mt++) {
        int row0 = bm + wm + mt * 16 + (lane >> 2);
#pragma unroll
        for (int nt = 0; nt < 4; nt++) {
            int col = bn + wn + nt * 8 + (lane & 3) * 2;
            float2* p0 = (float2*)(Out + (size_t)row0 * C_ + col);
            float2* p1 = (float2*)(Out + (size_t)(row0 + 8) * C_ + col);
            *p0 = make_float2(acc[mt][nt][0], acc[mt][nt][1]);
            *p1 = make_float2(acc[mt][nt][2], acc[mt][nt][3]);
        }
    }
}

// ---------------- fp32 -> fp16 hi/lo split ----------------
__global__ __launch_bounds__(256)
void split_fp16(const float* __restrict__ in, __half* __restrict__ hi,
                __half* __restrict__ lo, int n4)
{
    int i = blockIdx.x * blockDim.x + threadIdx.x;
    if (i >= n4) return;
    float4 v = ((const float4*)in)[i];
    __half h0 = __float2half_rn(v.x), h1 = __float2half_rn(v.y);
    __half h2 = __float2half_rn(v.z), h3 = __float2half_rn(v.w);
    __half2 hp0{h0, h1}, hp1{h2, h3};
    __half2 lp0{__float2half_rn(v.x - __half2float(h0)), __float2half_rn(v.y - __half2float(h1))};
    __half2 lp1{__float2half_rn(v.z - __half2float(h2)), __float2half_rn(v.w - __half2float(h3))};
    ((__half2*)hi)[i * 2 + 0] = hp0;
    ((__half2*)hi)[i * 2 + 1] = hp1;
    ((__half2*)lo)[i * 2 + 0] = lp0;
    ((__half2*)lo)[i * 2 + 1] = lp1;
}

// fp32 -> fp16 (weights)
__global__ __launch_bounds__(256)
void conv_fp16(const float* __restrict__ in, __half* __restrict__ out, int n4)
{
    int i = blockIdx.x * blockDim.x + threadIdx.x;
    if (i >= n4) return;
    float4 v = ((const float4*)in)[i];
    __half2 p0{__float2half_rn(v.x), __float2half_rn(v.y)};
    __half2 p1{__float2half_rn(v.z), __float2half_rn(v.w)};
    ((__half2*)out)[i * 2 + 0] = p0;
    ((__half2*)out)[i * 2 + 1] = p1;
}

// ---------------- WKV scan ----------------
#define PF 8
__global__ __launch_bounds__(128)
void wkv_scan_kernel(const float* __restrict__ time_decay,
                     const float* __restrict__ time_first)
{
    const int gid = blockIdx.x * blockDim.x + threadIdx.x;
    const int b = gid >> 10;
    const int c = gid & (C_ - 1);

    const float w = -__expf(time_decay[c]);
    const float u = time_first[c];

    float a = 0.f, bden = 0.f, pp = -1e38f;

    const float* kp = g_k + (size_t)b * T_ * C_ + c;
    const float* rp = g_r + (size_t)b * T_ * C_ + c;
    __half* shp = g_sh + (size_t)b * T_ * C_ + c;
    __half* slp = g_sl + (size_t)b * T_ * C_ + c;

    float kbuf[PF], rbuf[PF];
#pragma unroll
    for (int i = 0; i < PF; i++) {
        kbuf[i] = kp[(size_t)i * C_];
        rbuf[i] = rp[(size_t)i * C_];
    }

#pragma unroll 8
    for (int t = 0; t < T_; t++) {
        const float kt = kbuf[t & (PF - 1)];
        const float rt = rbuf[t & (PF - 1)];
        if (t + PF < T_) {
            kbuf[t & (PF - 1)] = kp[(size_t)(t + PF) * C_];
            rbuf[t & (PF - 1)] = rp[(size_t)(t + PF) * C_];
        }
        const float vt = rt;

        // output: q = max(pp, u+k); one of the exps is 1
        float ww = u + kt;
        float d  = pp - ww;
        float e  = __expf(-fabsf(d));
        float e1 = (d >= 0.f) ? 1.f : e;
        float e2 = (d >= 0.f) ? e : 1.f;
        float y  = __fdividef(e1 * a + e2 * vt, e1 * bden + e2);

        // state update
        float ww2 = pp + w;
        float d2  = ww2 - kt;
        float eb  = __expf(-fabsf(d2));
        float e1b = (d2 >= 0.f) ? 1.f : eb;
        float e2b = (d2 >= 0.f) ? eb : 1.f;
        a    = e1b * a + e2b * vt;
        bden = e1b * bden + e2b;
        pp   = fmaxf(ww2, kt);

        float sig = __fdividef(1.f, 1.f + __expf(-rt));
        float s = sig * y;
        __half h = __float2half_rn(s);
        shp[(size_t)t * C_] = h;
        slp[(size_t)t * C_] = __float2half_rn(s - __half2float(h));
    }
}

// ---------------- launch ----------------
extern "C" void kernel_launch(void* const* d_in, const int* in_sizes, int n_in,
                              void* d_out, int out_size)
{
    const float* x  = (const float*)d_in[0];
    const float* Wk = (const float*)d_in[1];
    const float* Wr = (const float*)d_in[2];
    const float* Wo = (const float*)d_in[3];
    const float* td = (const float*)d_in[4];
    const float* tf = (const float*)d_in[5];
    float* out = (float*)d_out;

    __half *xh, *xl, *wk, *wr, *wo, *sh, *sl;
    float *gk, *gr;
    cudaGetSymbolAddress((void**)&xh, g_xh); cudaGetSymbolAddress((void**)&xl, g_xl);
    cudaGetSymbolAddress((void**)&wk, g_wk); cudaGetSymbolAddress((void**)&wr, g_wr);
    cudaGetSymbolAddress((void**)&wo, g_wo);
    cudaGetSymbolAddress((void**)&sh, g_sh); cudaGetSymbolAddress((void**)&sl, g_sl);
    cudaGetSymbolAddress((void**)&gk, g_k);  cudaGetSymbolAddress((void**)&gr, g_r);

    cudaFuncSetAttribute(gemm_fp16x2, cudaFuncAttributeMaxDynamicSharedMemorySize, SMEM_GEMM);

    split_fp16<<<(M_ * C_ / 4 + 255) / 256, 256>>>(x, xh, xl, M_ * C_ / 4);
    conv_fp16<<<(C_ * C_ / 4 + 255) / 256, 256>>>(Wk, wk, C_ * C_ / 4);
    conv_fp16<<<(C_ * C_ / 4 + 255) / 256, 256>>>(Wr, wr, C_ * C_ / 4);
    conv_fp16<<<(C_ * C_ / 4 + 255) / 256, 256>>>(Wo, wo, C_ * C_ / 4);

    dim3 grid(C_ / BN, M_ / BM);   // (8, 128)
    gemm_fp16x2<<<grid, 256, SMEM_GEMM>>>(xh, xl, wk, gk);
    gemm_fp16x2<<<grid, 256, SMEM_GEMM>>>(xh, xl, wr, gr);
    wkv_scan_kernel<<<(B_ * C_) / 128, 128>>>(td, tf);
    gemm_fp16x2<<<grid, 256, SMEM_GEMM>>>(sh, sl, wo, out);
}